// round 6
// baseline (speedup 1.0000x reference)
#include <cuda_runtime.h>
#include <cstdint>

#define BB 4
#define HH 16
#define SSEQ 2048
#define DDIM 64
#define OUT_O_ELEMS ((size_t)BB * HH * SSEQ * DDIM)

#define KC 64                 // kv positions per chunk
#define NCH (SSEQ / KC)       // 32
#define STQ 68                // Q/K tf32 smem stride (floats)
#define STV 72                // V smem stride (floats)
#define STBW 36               // pass1 bf16 K stride (32-bit words = 72 bf16)

// ---- SMEM layout (bytes), phase-aliased ----
// phase A (load/pass1): Qs [0, 34816) ; B0 [34816, 44032) ; B1 [44032, 53248)
// phase B (pass2):      KS0 [0,17408) ; KS1 [17408,34816) ; VS [34816, 53248)
#define OFF_KS0 0
#define OFF_KS1 17408
#define OFF_VS  34816
#define OFF_B0  34816
#define OFF_B1  44032
#define SMEM_BYTES 53248      // x3 CTAs = 159.7KB <= 227KB

__device__ int g_maskFlag = 0;

__device__ __forceinline__ uint32_t f2tf32(float x) {
    uint32_t r;
    asm("cvt.rna.tf32.f32 %0, %1;" : "=r"(r) : "f"(x));
    return r;
}
__device__ __forceinline__ float tf(float x) { return __uint_as_float(f2tf32(x)); }
__device__ __forceinline__ uint32_t bfpack(float lo, float hi) {
    uint32_t r;
    asm("cvt.rn.bf16x2.f32 %0, %1, %2;" : "=r"(r) : "f"(hi), "f"(lo));
    return r;
}

__device__ __forceinline__ void mma_tf32(float* c,
                                         uint32_t a0, uint32_t a1, uint32_t a2, uint32_t a3,
                                         uint32_t b0, uint32_t b1) {
    asm volatile(
        "mma.sync.aligned.m16n8k8.row.col.f32.tf32.tf32.f32 "
        "{%0,%1,%2,%3}, {%4,%5,%6,%7}, {%8,%9}, {%0,%1,%2,%3};"
        : "+f"(c[0]), "+f"(c[1]), "+f"(c[2]), "+f"(c[3])
        : "r"(a0), "r"(a1), "r"(a2), "r"(a3), "r"(b0), "r"(b1));
}
__device__ __forceinline__ void mma_bf16(float* c,
                                         uint32_t a0, uint32_t a1, uint32_t a2, uint32_t a3,
                                         uint32_t b0, uint32_t b1) {
    asm volatile(
        "mma.sync.aligned.m16n8k16.row.col.f32.bf16.bf16.f32 "
        "{%0,%1,%2,%3}, {%4,%5,%6,%7}, {%8,%9}, {%0,%1,%2,%3};"
        : "+f"(c[0]), "+f"(c[1]), "+f"(c[2]), "+f"(c[3])
        : "r"(a0), "r"(a1), "r"(a2), "r"(a3), "r"(b0), "r"(b1));
}

__global__ void mask_check(const float* __restrict__ mask, size_t n) {
    size_t i = (size_t)blockIdx.x * blockDim.x + threadIdx.x;
    uint32_t any = 0;
    const size_t stride = (size_t)gridDim.x * blockDim.x;
    for (; i < n; i += stride) any |= __float_as_uint(mask[i]);
    if (__any_sync(0xffffffffu, any != 0u) && (threadIdx.x & 31) == 0)
        atomicOr(&g_maskFlag, 1);
}

// ============================================================
// Fused attention, 128 q-rows per CTA, 4 warps (warp tile 32 x KC).
// Pass1 (bf16 QK): l_row = sum_j exp(s).  Pass2 (tf32): recompute s,
// P = exp(s)*li -> gmem weights; P C-frag -> A-frag via shuffles; PV -> O.
// ============================================================
__global__ __launch_bounds__(128, 3)
void attn_fused(const float* __restrict__ q, const float* __restrict__ k,
                const float* __restrict__ v, const float* __restrict__ mask,
                float* __restrict__ out) {
    extern __shared__ float sm[];
    float* Qs = sm;                                  // phase A
    uint32_t* B0 = (uint32_t*)((char*)sm + OFF_B0);
    uint32_t* B1 = (uint32_t*)((char*)sm + OFF_B1);
    float* KS0 = (float*)((char*)sm + OFF_KS0);      // phase B
    float* KS1 = (float*)((char*)sm + OFF_KS1);
    float* VS  = (float*)((char*)sm + OFF_VS);

    const int tid = threadIdx.x;
    const int warp = tid >> 5, lane = tid & 31;
    const int grp = lane >> 2, tid4 = lane & 3;
    const int mt = blockIdx.x, bh = blockIdx.y;
    const int q0 = mt * 128;
    const int m0 = warp * 32;
    const size_t base = (size_t)bh * SSEQ * DDIM;
    const int mflag = *(volatile int*)&g_maskFlag;

    const int sl0 = (lane & 28) + (tid4 >> 1);   // P shuffle src lanes
    const int sl1 = sl0 + 2;
    const bool odd = (tid4 & 1);

    // ---- stage Q (pre-scaled 1/8, tf32-rounded) into smem ----
    {
        const float4* qg = (const float4*)(q + base + (size_t)q0 * DDIM);
        #pragma unroll
        for (int it = 0; it < 16; it++) {
            int j = tid + it * 128;
            int row = j >> 4, c = (j & 15) * 4;
            float4 v4 = qg[j];
            Qs[row * STQ + c]     = tf(v4.x * 0.125f);
            Qs[row * STQ + c + 1] = tf(v4.y * 0.125f);
            Qs[row * STQ + c + 2] = tf(v4.z * 0.125f);
            Qs[row * STQ + c + 3] = tf(v4.w * 0.125f);
        }
    }
    // ---- preload K chunk 0 as bf16 into B0 ----
    {
        const float4* kg = (const float4*)(k + base);
        #pragma unroll
        for (int i = 0; i < 8; i++) {
            int idx = tid + i * 128;
            int row = idx >> 4, w0 = (idx & 15) * 2;
            float4 a = kg[idx];
            B0[row * STBW + w0]     = bfpack(a.x, a.y);
            B0[row * STBW + w0 + 1] = bfpack(a.z, a.w);
        }
    }
    __syncthreads();

    // ---- build bf16 Q A-fragments (m16n8k16) from smem ----
    uint32_t qab[2][4][4];
    #pragma unroll
    for (int mf = 0; mf < 2; mf++) {
        const int r0 = m0 + mf * 16 + grp;
        #pragma unroll
        for (int t = 0; t < 4; t++) {
            const int k0 = t * 16 + tid4 * 2;
            qab[mf][t][0] = bfpack(Qs[r0 * STQ + k0],           Qs[r0 * STQ + k0 + 1]);
            qab[mf][t][1] = bfpack(Qs[(r0 + 8) * STQ + k0],     Qs[(r0 + 8) * STQ + k0 + 1]);
            qab[mf][t][2] = bfpack(Qs[r0 * STQ + k0 + 8],       Qs[r0 * STQ + k0 + 9]);
            qab[mf][t][3] = bfpack(Qs[(r0 + 8) * STQ + k0 + 8], Qs[(r0 + 8) * STQ + k0 + 9]);
        }
    }

    // ================= Pass 1: row sums (bf16 QK, kk-outer, 16 chains) ========
    float l[2][2] = {};
    for (int c = 0; c < NCH; c++) {
        uint32_t* cur = (c & 1) ? B1 : B0;
        uint32_t* nxt = (c & 1) ? B0 : B1;

        float4 pf[8];
        if (c + 1 < NCH) {
            const float4* kg = (const float4*)(k + base + (size_t)(c + 1) * KC * DDIM);
            #pragma unroll
            for (int i = 0; i < 8; i++) pf[i] = kg[tid + i * 128];
        }

        float s[8][2][4] = {};
        #pragma unroll
        for (int t = 0; t < 4; t++) {
            #pragma unroll
            for (int fn = 0; fn < 8; fn++) {
                uint32_t b0 = cur[(fn * 8 + grp) * STBW + t * 8 + tid4];
                uint32_t b1 = cur[(fn * 8 + grp) * STBW + t * 8 + tid4 + 4];
                mma_bf16(s[fn][0], qab[0][t][0], qab[0][t][1], qab[0][t][2], qab[0][t][3], b0, b1);
                mma_bf16(s[fn][1], qab[1][t][0], qab[1][t][1], qab[1][t][2], qab[1][t][3], b0, b1);
            }
        }
        #pragma unroll
        for (int fn = 0; fn < 8; fn++)
            #pragma unroll
            for (int mf = 0; mf < 2; mf++) {
                if (mflag) {
                    const float* mr0 = mask + (size_t)(q0 + m0 + mf * 16 + grp) * SSEQ + c * KC + fn * 8 + tid4 * 2;
                    const float* mr1 = mr0 + 8 * SSEQ;
                    float2 v0 = *(const float2*)mr0;
                    float2 v1 = *(const float2*)mr1;
                    s[fn][mf][0] += v0.x; s[fn][mf][1] += v0.y;
                    s[fn][mf][2] += v1.x; s[fn][mf][3] += v1.y;
                }
                l[mf][0] += __expf(s[fn][mf][0]) + __expf(s[fn][mf][1]);
                l[mf][1] += __expf(s[fn][mf][2]) + __expf(s[fn][mf][3]);
            }

        if (c + 1 < NCH) {
            #pragma unroll
            for (int i = 0; i < 8; i++) {
                int idx = tid + i * 128;
                int row = idx >> 4, w0 = (idx & 15) * 2;
                nxt[row * STBW + w0]     = bfpack(pf[i].x, pf[i].y);
                nxt[row * STBW + w0 + 1] = bfpack(pf[i].z, pf[i].w);
            }
        }
        __syncthreads();
    }
    float li[2][2];
    #pragma unroll
    for (int mf = 0; mf < 2; mf++)
        #pragma unroll
        for (int i = 0; i < 2; i++) {
            float x = l[mf][i];
            x += __shfl_xor_sync(0xffffffffu, x, 1);
            x += __shfl_xor_sync(0xffffffffu, x, 2);
            li[mf][i] = 1.f / x;
        }

    // ---- gather tf32 Q A-fragments (Qs still intact), then release region ----
    float qa[2][8][4];
    #pragma unroll
    for (int mf = 0; mf < 2; mf++) {
        const int r0 = m0 + mf * 16 + grp;
        #pragma unroll
        for (int kk = 0; kk < 8; kk++) {
            qa[mf][kk][0] = Qs[r0 * STQ + kk * 8 + tid4];
            qa[mf][kk][1] = Qs[(r0 + 8) * STQ + kk * 8 + tid4];
            qa[mf][kk][2] = Qs[r0 * STQ + kk * 8 + tid4 + 4];
            qa[mf][kk][3] = Qs[(r0 + 8) * STQ + kk * 8 + tid4 + 4];
        }
    }
    __syncthreads();

    // ---- stage K chunk 0 (tf32) into KS0 ----
    {
        const float4* kg = (const float4*)(k + base);
        #pragma unroll
        for (int i = 0; i < 8; i++) {
            int idx = tid + i * 128;
            int row = idx >> 4, cc = (idx & 15) * 4;
            float4 a = kg[idx];
            *(float4*)&KS0[row * STQ + cc] = make_float4(tf(a.x), tf(a.y), tf(a.z), tf(a.w));
        }
    }

    // ================= Pass 2: weights + P·V =================
    float o[2][8][4] = {};
    float* wb = out + OUT_O_ELEMS + (size_t)bh * SSEQ * SSEQ + (size_t)q0 * SSEQ;

    for (int c = 0; c < NCH; c++) {
        float* KSc = (c & 1) ? KS1 : KS0;
        float* KSn = (c & 1) ? KS0 : KS1;
        const float4* kg1 = (const float4*)(k + base + (size_t)(c + 1) * KC * DDIM);

        __syncthreads();   // all warps done with chunk c-1 (VS, KSn reads)

        // prefetch first half of K_{c+1}
        float4 pf[4];
        if (c + 1 < NCH) {
            #pragma unroll
            for (int i = 0; i < 4; i++) pf[i] = kg1[tid + i * 128];
        }
        // stage V_c (tf32)
        {
            const float4* vg = (const float4*)(v + base + (size_t)c * KC * DDIM);
            #pragma unroll
            for (int i = 0; i < 8; i++) {
                int idx = tid + i * 128;
                int row = idx >> 4, cc = (idx & 15) * 4;
                float4 a = vg[idx];
                *(float4*)&VS[row * STV + cc] = make_float4(tf(a.x), tf(a.y), tf(a.z), tf(a.w));
            }
        }
        __syncthreads();   // VS visible

        #pragma unroll
        for (int fnh = 0; fnh < 2; fnh++) {
            #pragma unroll
            for (int fn4 = 0; fn4 < 4; fn4++) {
                const int fn = fnh * 4 + fn4;
                // --- QK^T recompute (tf32) for this 8-col block ---
                float s[2][4] = {};
                #pragma unroll
                for (int kk = 0; kk < 8; kk++) {
                    uint32_t b0 = __float_as_uint(KSc[(fn * 8 + grp) * STQ + kk * 8 + tid4]);
                    uint32_t b1 = __float_as_uint(KSc[(fn * 8 + grp) * STQ + kk * 8 + tid4 + 4]);
                    mma_tf32(s[0], __float_as_uint(qa[0][kk][0]), __float_as_uint(qa[0][kk][1]),
                                   __float_as_uint(qa[0][kk][2]), __float_as_uint(qa[0][kk][3]), b0, b1);
                    mma_tf32(s[1], __float_as_uint(qa[1][kk][0]), __float_as_uint(qa[1][kk][1]),
                                   __float_as_uint(qa[1][kk][2]), __float_as_uint(qa[1][kk][3]), b0, b1);
                }
                #pragma unroll
                for (int mf = 0; mf < 2; mf++) {
                    const int r0 = m0 + mf * 16 + grp;
                    if (mflag) {
                        const float* mr0 = mask + (size_t)(q0 + r0) * SSEQ + c * KC + fn * 8 + tid4 * 2;
                        const float* mr1 = mr0 + 8 * SSEQ;
                        float2 v0 = *(const float2*)mr0;
                        float2 v1 = *(const float2*)mr1;
                        s[mf][0] += v0.x; s[mf][1] += v0.y; s[mf][2] += v1.x; s[mf][3] += v1.y;
                    }
                    float p0 = __expf(s[mf][0]) * li[mf][0];
                    float p1 = __expf(s[mf][1]) * li[mf][0];
                    float p2 = __expf(s[mf][2]) * li[mf][1];
                    float p3 = __expf(s[mf][3]) * li[mf][1];

                    float* w0 = wb + (size_t)r0 * SSEQ + c * KC + fn * 8 + tid4 * 2;
                    *(float2*)w0 = make_float2(p0, p1);
                    *(float2*)(w0 + 8 * SSEQ) = make_float2(p2, p3);

                    // C-frag -> A-frag via shuffles
                    float x0 = __shfl_sync(0xffffffffu, p0, sl0);
                    float x1 = __shfl_sync(0xffffffffu, p1, sl0);
                    float x2 = __shfl_sync(0xffffffffu, p2, sl0);
                    float x3 = __shfl_sync(0xffffffffu, p3, sl0);
                    float y0 = __shfl_sync(0xffffffffu, p0, sl1);
                    float y1 = __shfl_sync(0xffffffffu, p1, sl1);
                    float y2 = __shfl_sync(0xffffffffu, p2, sl1);
                    float y3 = __shfl_sync(0xffffffffu, p3, sl1);
                    uint32_t a0 = f2tf32(odd ? x1 : x0);
                    uint32_t a1 = f2tf32(odd ? x3 : x2);
                    uint32_t a2 = f2tf32(odd ? y1 : y0);
                    uint32_t a3 = f2tf32(odd ? y3 : y2);

                    // P·V for this k-block
                    #pragma unroll
                    for (int nb = 0; nb < 8; nb++) {
                        uint32_t b0 = __float_as_uint(VS[(fn * 8 + tid4) * STV + nb * 8 + grp]);
                        uint32_t b1 = __float_as_uint(VS[(fn * 8 + tid4 + 4) * STV + nb * 8 + grp]);
                        mma_tf32(o[mf][nb], a0, a1, a2, a3, b0, b1);
                    }
                }
            }
            // between halves: consume pfA -> KSn, issue pfB
            if (fnh == 0 && c + 1 < NCH) {
                #pragma unroll
                for (int i = 0; i < 4; i++) {
                    int idx = tid + i * 128;
                    int row = idx >> 4, cc = (idx & 15) * 4;
                    *(float4*)&KSn[row * STQ + cc] =
                        make_float4(tf(pf[i].x), tf(pf[i].y), tf(pf[i].z), tf(pf[i].w));
                }
                #pragma unroll
                for (int i = 0; i < 4; i++) pf[i] = kg1[tid + (i + 4) * 128];
            }
        }
        // consume pfB -> KSn (rows 32..63)
        if (c + 1 < NCH) {
            #pragma unroll
            for (int i = 0; i < 4; i++) {
                int idx = tid + (i + 4) * 128;
                int row = idx >> 4, cc = (idx & 15) * 4;
                *(float4*)&KSn[row * STQ + cc] =
                    make_float4(tf(pf[i].x), tf(pf[i].y), tf(pf[i].z), tf(pf[i].w));
            }
        }
    }

    // ---- write O ----
    float* ob = out + base + (size_t)q0 * DDIM;
    #pragma unroll
    for (int mf = 0; mf < 2; mf++) {
        const int r0 = m0 + mf * 16 + grp;
        #pragma unroll
        for (int nb = 0; nb < 8; nb++) {
            int col = nb * 8 + tid4 * 2;
            *(float2*)&ob[(size_t)r0 * DDIM + col]       = make_float2(o[mf][nb][0], o[mf][nb][1]);
            *(float2*)&ob[(size_t)(r0 + 8) * DDIM + col] = make_float2(o[mf][nb][2], o[mf][nb][3]);
        }
    }
}

extern "C" void kernel_launch(void* const* d_in, const int* in_sizes, int n_in,
                              void* d_out, int out_size) {
    const float* q    = (const float*)d_in[0];
    const float* k    = (const float*)d_in[1];
    const float* v    = (const float*)d_in[2];
    const float* mask = (const float*)d_in[3];
    float* out = (float*)d_out;

    cudaFuncSetAttribute(attn_fused, cudaFuncAttributeMaxDynamicSharedMemorySize, SMEM_BYTES);

    mask_check<<<128, 256>>>(mask, (size_t)SSEQ * SSEQ);
    attn_fused<<<dim3(16, BB * HH), 128, SMEM_BYTES>>>(q, k, v, mask, out);
}